// round 3
// baseline (speedup 1.0000x reference)
#include <cuda_runtime.h>
#include <cuda_bf16.h>

#define NN 8192
#define ECAP (1u << 22)   // 4M edge slots (16MB static) — ~50x headroom over ~78k

// Static scratch (no allocation allowed)
__device__ int d_parent[NN];
__device__ unsigned int d_nedges;     // strictly-upper positives == union edges
__device__ unsigned int d_dcount;     // diagonal positives
__device__ unsigned int d_edges[ECAP];

__global__ void hc_init_kernel() {
    int i = blockIdx.x * blockDim.x + threadIdx.x;
    if (i < NN) d_parent[i] = i;
    if (i == 0) { d_nedges = 0u; d_dcount = 0u; }
}

// Lock-free union-find (path halving + CAS hooking toward smaller root).
__device__ __noinline__ void uf_union(int a, int b) {
    while (true) {
        while (true) {                       // find(a)
            int p = d_parent[a];
            if (p == a) break;
            int gp = d_parent[p];
            if (gp == p) { a = p; break; }
            d_parent[a] = gp; a = gp;
        }
        while (true) {                       // find(b)
            int p = d_parent[b];
            if (p == b) break;
            int gp = d_parent[p];
            if (gp == p) { b = p; break; }
            d_parent[b] = gp; b = gp;
        }
        if (a == b) return;
        int lo = min(a, b);
        int hi = max(a, b);
        int old = atomicCAS(&d_parent[hi], hi, lo);
        if (old == hi) return;
        a = lo;
        b = old;
    }
}

// Rare path: append strictly-upper positive entries of one quad as edges.
__device__ __forceinline__ void emit_quad(int row, int col0, float4 v) {
    unsigned k = (unsigned)(v.x > 0.0f) + (unsigned)(v.y > 0.0f) +
                 (unsigned)(v.z > 0.0f) + (unsigned)(v.w > 0.0f);
    unsigned base = atomicAdd(&d_nedges, k);
    unsigned enc = ((unsigned)row << 16);
    if (v.x > 0.0f) { if (base < ECAP) d_edges[base] = enc | (unsigned)(col0 + 0); else uf_union(row, col0 + 0); base++; }
    if (v.y > 0.0f) { if (base < ECAP) d_edges[base] = enc | (unsigned)(col0 + 1); else uf_union(row, col0 + 1); base++; }
    if (v.z > 0.0f) { if (base < ECAP) d_edges[base] = enc | (unsigned)(col0 + 2); else uf_union(row, col0 + 2); base++; }
    if (v.w > 0.0f) { if (base < ECAP) d_edges[base] = enc | (unsigned)(col0 + 3); else uf_union(row, col0 + 3); base++; }
}

// Upper-triangle scan. Block b handles row pair (b, NN-1-b) -> NN+1 elements
// per block, perfectly balanced. Hot loop per quad: LDG.128 + fmax tree +
// 1 compare + rarely-taken branch. Counts/unions are deferred to the edge
// buffer; diagonal positives counted from the diagonal quad (thread 0).
__global__ void hc_scan_upper(const float* __restrict__ adj) {
    const int pair = blockIdx.x;
    const int t = threadIdx.x;

    #pragma unroll
    for (int half = 0; half < 2; half++) {
        const int row = (half == 0) ? pair : (NN - 1 - pair);
        const float4* __restrict__ rowp = (const float4*)(adj + (size_t)row * NN);
        const int start4 = row >> 2;

        if (t == 0) {
            // quad containing the diagonal: handle cols == row and > row
            float4 v = rowp[start4];
            int col0 = start4 << 2;
            float e[4] = {v.x, v.y, v.z, v.w};
            unsigned dd = 0;
            #pragma unroll
            for (int j = 0; j < 4; j++) {
                int col = col0 + j;
                if (e[j] > 0.0f) {
                    if (col == row) dd++;
                    else if (col > row) {
                        unsigned base = atomicAdd(&d_nedges, 1u);
                        if (base < ECAP) d_edges[base] = ((unsigned)row << 16) | (unsigned)col;
                        else uf_union(row, col);
                    }
                }
            }
            if (dd) atomicAdd(&d_dcount, dd);
        }

        #pragma unroll 4
        for (int idx4 = start4 + 1 + t; idx4 < NN / 4; idx4 += 256) {
            float4 v = rowp[idx4];
            float m = fmaxf(fmaxf(v.x, v.y), fmaxf(v.z, v.w));
            if (m > 0.0f) {
                emit_quad(row, idx4 << 2, v);
            }
        }
    }
}

__global__ void hc_union_kernel() {
    unsigned n = d_nedges;
    if (n > ECAP) n = ECAP;
    unsigned stride = gridDim.x * blockDim.x;
    for (unsigned i = blockIdx.x * blockDim.x + threadIdx.x; i < n; i += stride) {
        unsigned e = d_edges[i];
        uf_union((int)(e >> 16), (int)(e & 0xFFFFu));
    }
}

__global__ void hc_finish_kernel(float* __restrict__ out) {
    __shared__ int sh[256];
    int t = threadIdx.x;
    int roots = 0;
    for (int i = t; i < NN; i += 256)
        roots += (d_parent[i] == i) ? 1 : 0;
    sh[t] = roots;
    __syncthreads();
    for (int s = 128; s > 0; s >>= 1) {
        if (t < s) sh[t] += sh[t + s];
        __syncthreads();
    }
    if (t == 0) {
        float n_comp  = (float)sh[0];
        // full-matrix positives = 2U + D; reference //2 -> U + D//2 exactly
        unsigned int half_edges = d_nedges + (d_dcount >> 1);
        float n_edges = (float)half_edges;
        float betti1  = n_edges - (float)NN + n_comp;
        float n_cyc   = fmaxf(0.0f, betti1);
        float comp_l  = (n_comp - 1.0f) * (n_comp - 1.0f);
        out[0] = comp_l + n_cyc * n_cyc;
    }
}

extern "C" void kernel_launch(void* const* d_in, const int* in_sizes, int n_in,
                              void* d_out, int out_size) {
    const float* adj = (const float*)d_in[0];
    float* out = (float*)d_out;

    hc_init_kernel<<<(NN + 255) / 256, 256>>>();
    hc_scan_upper<<<NN / 2, 256>>>(adj);
    hc_union_kernel<<<64, 256>>>();
    hc_finish_kernel<<<1, 256>>>(out);
}

// round 4
// speedup vs baseline: 1.8467x; 1.8467x over previous
#include <cuda_runtime.h>
#include <cuda_bf16.h>

#define NN 8192

// Static scratch (no allocation allowed anywhere)
__device__ int d_parent[NN];
__device__ unsigned int d_ucount;   // strictly-upper positives
__device__ unsigned int d_dcount;   // diagonal positives

__global__ void hc_init_kernel() {
    int i = blockIdx.x * blockDim.x + threadIdx.x;
    if (i < NN) d_parent[i] = i;
    if (i == 0) { d_ucount = 0u; d_dcount = 0u; }
}

// Lock-free union-find: path halving + CAS hooking toward smaller root.
// __noinline__ keeps this cold path out of the streaming loop.
__device__ __noinline__ void uf_union(int a, int b) {
    while (true) {
        while (true) {                       // find(a)
            int p = d_parent[a];
            if (p == a) break;
            int gp = d_parent[p];
            if (gp == p) { a = p; break; }
            d_parent[a] = gp; a = gp;
        }
        while (true) {                       // find(b)
            int p = d_parent[b];
            if (p == b) break;
            int gp = d_parent[p];
            if (gp == p) { b = p; break; }
            d_parent[b] = gp; b = gp;
        }
        if (a == b) return;
        int lo = min(a, b);
        int hi = max(a, b);
        int old = atomicCAS(&d_parent[hi], hi, lo);
        if (old == hi) return;
        a = lo;
        b = old;
    }
}

// Cold path: union the positive elements of one quad (all cols > row here).
__device__ __noinline__ void union_quad(int row, int col0, float4 v) {
    if (v.x > 0.0f) uf_union(row, col0 + 0);
    if (v.y > 0.0f) uf_union(row, col0 + 1);
    if (v.z > 0.0f) uf_union(row, col0 + 2);
    if (v.w > 0.0f) uf_union(row, col0 + 3);
}

// Upper-triangle scan. Block b handles the row pair (b, NN-1-b): NN+1
// elements per block -> perfect balance. Hot loop: 4 independent LDG.128
// batched up front (MLP_p1 = 4), straight-line predicate counting, and a
// single rarely-taken branch per 16 elements for unions. Past the diagonal
// quad, col > row always holds, so no column compares in the hot loop.
// Exactness: adj is bitwise symmetric -> full positives = 2U + D, and
// reference n_edges = (2U+D)//2 = U + D//2.
__global__ void hc_scan_upper(const float* __restrict__ adj) {
    const int pair = blockIdx.x;
    const int t = threadIdx.x;
    unsigned int cnt = 0;

    #pragma unroll
    for (int half = 0; half < 2; half++) {
        const int row = half ? (NN - 1 - pair) : pair;
        const float4* __restrict__ rowp = (const float4*)(adj + (size_t)row * NN);
        const int start4 = row >> 2;         // quad containing the diagonal

        if (t == 0) {
            // diagonal quad: cols may be <, ==, or > row
            float4 v = rowp[start4];
            int col0 = start4 << 2;
            float e[4] = {v.x, v.y, v.z, v.w};
            unsigned dd = 0;
            #pragma unroll
            for (int j = 0; j < 4; j++) {
                int col = col0 + j;
                if (e[j] > 0.0f) {
                    if (col == row) dd++;
                    else if (col > row) { cnt++; uf_union(row, col); }
                }
            }
            if (dd) atomicAdd(&d_dcount, dd);
        }

        const int lim = NN / 4;
        for (int i0 = start4 + 1 + t; i0 < lim; i0 += 1024) {
            const float4 NEG = make_float4(-1.f, -1.f, -1.f, -1.f);
            // Batch 4 independent loads before any use (predicated, no branch)
            float4 v0 = rowp[i0];
            float4 v1 = NEG, v2 = NEG, v3 = NEG;
            if (i0 + 256 < lim) v1 = rowp[i0 + 256];
            if (i0 + 512 < lim) v2 = rowp[i0 + 512];
            if (i0 + 768 < lim) v3 = rowp[i0 + 768];

            // exact positive count (straight-line, no branches)
            cnt += (unsigned)(v0.x > 0.f) + (unsigned)(v0.y > 0.f)
                 + (unsigned)(v0.z > 0.f) + (unsigned)(v0.w > 0.f);
            cnt += (unsigned)(v1.x > 0.f) + (unsigned)(v1.y > 0.f)
                 + (unsigned)(v1.z > 0.f) + (unsigned)(v1.w > 0.f);
            cnt += (unsigned)(v2.x > 0.f) + (unsigned)(v2.y > 0.f)
                 + (unsigned)(v2.z > 0.f) + (unsigned)(v2.w > 0.f);
            cnt += (unsigned)(v3.x > 0.f) + (unsigned)(v3.y > 0.f)
                 + (unsigned)(v3.z > 0.f) + (unsigned)(v3.w > 0.f);

            // one rare branch per 16 elements for the union path
            float m0 = fmaxf(fmaxf(v0.x, v0.y), fmaxf(v0.z, v0.w));
            float m1 = fmaxf(fmaxf(v1.x, v1.y), fmaxf(v1.z, v1.w));
            float m2 = fmaxf(fmaxf(v2.x, v2.y), fmaxf(v2.z, v2.w));
            float m3 = fmaxf(fmaxf(v3.x, v3.y), fmaxf(v3.z, v3.w));
            if (fmaxf(fmaxf(m0, m1), fmaxf(m2, m3)) > 0.f) {
                if (m0 > 0.f) union_quad(row, (i0      ) << 2, v0);
                if (m1 > 0.f) union_quad(row, (i0 + 256) << 2, v1);
                if (m2 > 0.f) union_quad(row, (i0 + 512) << 2, v2);
                if (m3 > 0.f) union_quad(row, (i0 + 768) << 2, v3);
            }
        }
    }

    // warp reduce, then block reduce -> 1 atomic per block
    for (int s = 16; s > 0; s >>= 1)
        cnt += __shfl_down_sync(0xFFFFFFFFu, cnt, s);
    __shared__ unsigned int shu[8];
    int lane = t & 31, w = t >> 5;
    if (lane == 0) shu[w] = cnt;
    __syncthreads();
    if (t == 0) {
        unsigned int su = 0;
        #pragma unroll
        for (int i = 0; i < 8; i++) su += shu[i];
        atomicAdd(&d_ucount, su);
    }
}

__global__ void hc_finish_kernel(float* __restrict__ out) {
    __shared__ int sh[256];
    int t = threadIdx.x;
    int roots = 0;
    for (int i = t; i < NN; i += 256)
        roots += (d_parent[i] == i) ? 1 : 0;
    sh[t] = roots;
    __syncthreads();
    for (int s = 128; s > 0; s >>= 1) {
        if (t < s) sh[t] += sh[t + s];
        __syncthreads();
    }
    if (t == 0) {
        float n_comp  = (float)sh[0];
        unsigned int half_edges = d_ucount + (d_dcount >> 1);  // (2U+D)//2
        float n_edges = (float)half_edges;
        float betti1  = n_edges - (float)NN + n_comp;
        float n_cyc   = fmaxf(0.0f, betti1);
        float comp_l  = (n_comp - 1.0f) * (n_comp - 1.0f);
        out[0] = comp_l + n_cyc * n_cyc;
    }
}

extern "C" void kernel_launch(void* const* d_in, const int* in_sizes, int n_in,
                              void* d_out, int out_size) {
    const float* adj = (const float*)d_in[0];
    float* out = (float*)d_out;

    hc_init_kernel<<<(NN + 255) / 256, 256>>>();
    hc_scan_upper<<<NN / 2, 256>>>(adj);
    hc_finish_kernel<<<1, 256>>>(out);
}